// round 16
// baseline (speedup 1.0000x reference)
#include <cuda_runtime.h>
#include <cuda_bf16.h>
#include <math.h>

#define GRID_N 4096

// ---- Bit-exact replica of XLA:CPU GenerateVF32Exp (validated R0-R15) ----
__device__ __forceinline__ float exp_xla_cpu(float input) {
    const float exp_hi = 88.3762626647950f;
    const float exp_lo = -88.3762626647949f;
    const float LOG2EF = 1.44269504088896341f;
    const float C1 = 0.693359375f;
    const float C2 = -2.12194440e-4f;
    const float p0 = 1.9875691500E-4f;
    const float p1 = 1.3981999507E-3f;
    const float p2 = 8.3334519073E-3f;
    const float p3 = 4.1665795894E-2f;
    const float p4 = 1.6666665459E-1f;
    const float p5 = 5.0000001201E-1f;

    float xc = fminf(fmaxf(input, exp_lo), exp_hi);
    float fx = floorf(__fmaf_rn(xc, LOG2EF, 0.5f));
    float tmp = __fmul_rn(C1, fx);
    float z   = __fmul_rn(C2, fx);
    float x   = __fsub_rn(xc, tmp);
    x = __fsub_rn(x, z);
    float z2 = __fmul_rn(x, x);

    float y = __fmaf_rn(x, p0, p1);
    y = __fmaf_rn(y, x, p2);
    y = __fmaf_rn(y, x, p3);
    y = __fmaf_rn(y, x, p4);
    y = __fmaf_rn(y, x, p5);
    y = __fmaf_rn(y, z2, x);
    y = __fadd_rn(y, 1.0f);

    int emm0 = (int)fx;
    emm0 = (emm0 + 0x7f) << 23;
    float two_m = __int_as_float(emm0);

    return fmaxf(__fmul_rn(y, two_m), input);
}

__device__ __forceinline__ float sigm(float v) {
    float e = exp_xla_cpu(-v);
    return __fdiv_rn(1.0f, __fadd_rn(1.0f, e));
}

__device__ __forceinline__ float relu_f(float v) { return fmaxf(v, 0.0f); }

// Windowed _gen_index, direct __ldg. g is monotone (linspace), so the
// first-occurrence argmin of |ac-g[i]| lies within +-4 of the analytic
// crossing; the clamped 9-wide window reproduces the EXACT index. hi/lo
// resolve from window registers when possible (identical float values).
__device__ float gen_index_window(const float* __restrict__ g,
                                  float g0, float gl, float a) {
    const float rstep = 1.0f / 2047.5f;  // fl(1/2047.5) (XLA const-div rewrite)
    float ac = fminf(fmaxf(a, gl), g0);

    float frac = __fdiv_rn(__fsub_rn(g0, ac), __fsub_rn(g0, gl));
    int c = __float2int_rn(__fmul_rn(frac, 4095.0f));

    int idxs[9];
    float vals[9];
#pragma unroll
    for (int k = 0; k < 9; k++) {
        int i = c - 4 + k;
        i = i < 0 ? 0 : (i > GRID_N - 1 ? GRID_N - 1 : i);
        idxs[k] = i;
        vals[k] = __ldg(&g[i]);   // 9 independent loads, batched
    }

    float best = __int_as_float(0x7f800000);
    int arg = idxs[0];
    float garg = vals[0];
    int argk = 0;
#pragma unroll
    for (int k = 0; k < 9; k++) {
        float d = fabsf(__fsub_rn(ac, vals[k]));
        // strict < keeps first (lowest-index) occurrence == jnp.argmin
        if (d < best) { best = d; arg = idxs[k]; garg = vals[k]; argk = k; }
    }

    int shift = (garg > ac) ? 1 : 0;
    arg += shift;

    // hi = g[arg-1] (JAX wrap -1 -> last), lo = g[min(arg, N-1)].
    float hi, lo;
    int km1 = argk + shift - 1;
    int k0  = argk + shift;
    bool fast = (km1 >= 0) && (k0 <= 8) &&
                (idxs[km1] == arg - 1) && (idxs[k0] == arg) &&
                (arg >= 1) && (arg <= GRID_N - 1);
    if (fast) {
        hi = vals[km1];
        lo = vals[k0];
    } else {
        hi = (arg == 0) ? gl : __ldg(&g[arg - 1]);
        int lo_idx = arg > GRID_N - 1 ? GRID_N - 1 : arg;
        lo = __ldg(&g[lo_idx]);
    }

    float A = __fmul_rn(__fdiv_rn(__fsub_rn(hi, ac), __fsub_rn(hi, lo)), rstep);
    float B = __fmul_rn((float)(arg - 1), rstep);
    return __fsub_rn(__fadd_rn(A, B), 1.0f);
}

// Reference _bilinear on a [4096,4096] row-major table.
__device__ float bilinear(const float* __restrict__ t, float gx, float gy) {
    const float Wm1 = 4095.0f;
    float pxr = __fmul_rn(__fmul_rn(__fadd_rn(gx, 1.0f), 0.5f), Wm1);
    float pyr = __fmul_rn(__fmul_rn(__fadd_rn(gy, 1.0f), 0.5f), Wm1);
    float px = fminf(fmaxf(pxr, 0.0f), Wm1);
    float py = fminf(fmaxf(pyr, 0.0f), Wm1);
    float x0f = floorf(px);
    float y0f = floorf(py);
    float wx = __fsub_rn(px, x0f);
    float wy = __fsub_rn(py, y0f);
    float omwx = __fsub_rn(1.0f, wx);
    float omwy = __fsub_rn(1.0f, wy);
    int x0 = (int)x0f; x0 = max(0, min(x0, GRID_N - 1));
    int x1 = min(x0 + 1, GRID_N - 1);
    int y0 = (int)y0f; y0 = max(0, min(y0, GRID_N - 1));
    int y1 = min(y0 + 1, GRID_N - 1);
    float t00 = __ldg(&t[(long)y0 * GRID_N + x0]);
    float t01 = __ldg(&t[(long)y0 * GRID_N + x1]);
    float t10 = __ldg(&t[(long)y1 * GRID_N + x0]);
    float t11 = __ldg(&t[(long)y1 * GRID_N + x1]);
    float m00 = __fmul_rn(__fmul_rn(t00, omwx), omwy);
    float m01 = __fmul_rn(__fmul_rn(t01, wx), omwy);
    float m10 = __fmul_rn(__fmul_rn(t10, omwx), wy);
    float m11 = __fmul_rn(__fmul_rn(t11, wx), wy);
    return __fadd_rn(__fadd_rn(__fadd_rn(m00, m01), m10), m11);
}

// com slots: [0..4] gi1  [5..10] sigm(tw)  [11..14] sigm(tw2)
// [15..17] alpha1  [18..20] alpha2  [21..23] flags  [24..29] ybuf
// [34..37] gi2     [40] regu_total

__global__ void __launch_bounds__(32, 1)
rnn_kernel(const float* __restrict__ x,
           const float* __restrict__ s_weight,
           const float* __restrict__ t_weight,
           const float* __restrict__ t_weight2,
           const float* __restrict__ g,
           const float* __restrict__ res1,
           const float* __restrict__ res2,
           const float* __restrict__ alpha1,
           const float* __restrict__ alpha2,
           const float* __restrict__ soa_res1,
           const float* __restrict__ soa_res2,
           float* __restrict__ out, int out_size) {
    __shared__ float com[48];
    int lane = threadIdx.x;

    // Grid endpoints (independent loads, issue immediately on all lanes).
    float g0 = __ldg(&g[0]);
    float gl = __ldg(&g[GRID_N - 1]);

    // ---- Phase 0: scalar loads + sigmoids + stage-1 gen_index ----
    if (lane < 5) {
        float a = (lane < 3) ? __ldg(&x[lane * 2 + 1])
                             : sigm(__ldg(&s_weight[lane - 3]));
        com[lane] = gen_index_window(g, g0, gl, a);
    } else if (lane < 11) {
        com[lane] = sigm(__ldg(&t_weight[lane - 5]));
    } else if (lane < 15) {
        com[lane] = sigm(__ldg(&t_weight2[lane - 11]));
    } else if (lane < 18) {
        com[lane] = __ldg(&alpha1[lane - 15]);
    } else if (lane < 21) {
        com[lane] = __ldg(&alpha2[lane - 18]);
    } else if (lane < 24) {
        com[lane] = __ldg(&x[(lane - 21) * 2]);
    }
    __syncwarp();

    // ---- Phase 1: stage-1 bilinear (lanes 0-5) ----
    if (lane < 6) {
        int i = lane % 3;
        const float* tab = (lane < 3) ? res1 : res2;
        float gx = (lane < 3) ? com[3] : com[4];
        com[24 + lane] = bilinear(tab, gx, com[i]);
    }
    __syncwarp();

    // ---- Phase 2+3: lanes 0-4 recompute yvec locally (bit-identical),
    // lanes 0-3 stage-2 gen_index, lane 4 regu ----
    if (lane < 5) {
        float w1[3], w2[3];
#pragma unroll
        for (int i = 0; i < 3; i++) {
            float flag = com[21 + i];
            float s1 = (flag == 1.0f) ? com[24 + i] : 0.0f;
            float s2 = (flag == 2.0f) ? com[27 + i] : 0.0f;
            w1[i] = __fmul_rn(s1, com[15 + i]);
            w2[i] = __fmul_rn(s2, com[18 + i]);
        }
        float y1v[2], y2v[2];
#pragma unroll
        for (int j = 0; j < 2; j++) {
            float tw0 = com[5 + 0 * 2 + j];
            float tw1 = com[5 + 1 * 2 + j];
            float tw2 = com[5 + 2 * 2 + j];
            y1v[j] = __fmaf_rn(w1[2], tw2,
                      __fmaf_rn(w1[1], tw1, __fmul_rn(w1[0], tw0)));
            y2v[j] = __fmaf_rn(w2[2], tw2,
                      __fmaf_rn(w2[1], tw1, __fmul_rn(w2[0], tw0)));
        }

        if (lane < 4) {
            // lane0: y1v[0], lane1: y2v[0], lane2: y1v[1], lane3: y2v[1]
            float a = (lane & 1) ? y2v[lane >> 1] : y1v[lane >> 1];
            com[34 + lane] = gen_index_window(g, g0, gl, a);
        } else {
            float a10 = y1v[0], a11 = y1v[1];
            float a20 = y2v[0], a21 = y2v[1];
            float tA, tB, r1a, r1b, r2a, r2b;
            tA = relu_f(__fsub_rn(__fsub_rn(a10, g0), 0.001f));
            tB = relu_f(__fsub_rn(__fadd_rn(gl, 0.001f), a10));
            r1a = __fdiv_rn(__fadd_rn(tA, tB), __fmul_rn(a10, 2.0f));
            tA = relu_f(__fsub_rn(__fsub_rn(a20, g0), 0.001f));
            tB = relu_f(__fsub_rn(__fadd_rn(gl, 0.001f), a20));
            r1b = __fdiv_rn(__fadd_rn(tA, tB), __fmul_rn(a20, 2.0f));
            tA = relu_f(__fsub_rn(__fsub_rn(a11, g0), 0.001f));
            tB = relu_f(__fsub_rn(__fadd_rn(gl, 0.001f), a11));
            r2a = __fdiv_rn(__fadd_rn(tA, tB), __fmul_rn(a11, 2.0f));
            tA = relu_f(__fsub_rn(__fsub_rn(a21, g0), 0.001f));
            tB = relu_f(__fsub_rn(__fadd_rn(gl, 0.001f), a21));
            r2b = __fdiv_rn(__fadd_rn(tA, tB), __fmul_rn(a21, 2.0f));
            float regu1 = __fadd_rn(r1a, r1b);
            float regu2 = __fadd_rn(r2a, r2b);
            com[40] = __fadd_rn(regu1, regu2);
        }
    }
    __syncwarp();

    // ---- Phase 4: stage-2 bilinear (lanes 0-1), shfl combine, store ----
    float ys = 0.0f;
    if (lane < 2) {
        const float* tab = (lane == 0) ? soa_res1 : soa_res2;
        ys = bilinear(tab, com[34 + lane * 2 + 1], com[34 + lane * 2]);
    }
    float ys_other = __shfl_sync(0xffffffffu, ys, 1);

    if (lane == 0) {
        float y_1 = ys;
        float y_2 = ys_other;
        float tw00 = com[11], tw01 = com[12];
        float tw10 = com[13], tw11 = com[14];

        float o0 = __fmaf_rn(y_2, tw10, __fmul_rn(y_1, tw00));
        float o1 = __fmaf_rn(y_2, tw11, __fmul_rn(y_1, tw01));
        float o2 = com[40];

        if (out_size > 0) out[0] = o0;
        if (out_size > 1) out[1] = o1;
        if (out_size > 2) out[2] = o2;
    }
}

extern "C" void kernel_launch(void* const* d_in, const int* in_sizes, int n_in,
                              void* d_out, int out_size) {
    const float* x         = (const float*)d_in[0];
    const float* s_weight  = (const float*)d_in[1];
    const float* t_weight  = (const float*)d_in[2];
    const float* t_weight2 = (const float*)d_in[3];
    const float* g         = (const float*)d_in[4];
    const float* res1      = (const float*)d_in[5];
    const float* res2      = (const float*)d_in[6];
    const float* alpha1    = (const float*)d_in[7];
    const float* alpha2    = (const float*)d_in[8];
    const float* soa_res1  = (const float*)d_in[9];
    const float* soa_res2  = (const float*)d_in[10];
    float* out = (float*)d_out;

    rnn_kernel<<<1, 32>>>(x, s_weight, t_weight, t_weight2, g, res1, res2,
                          alpha1, alpha2, soa_res1, soa_res2, out, out_size);
}

// round 17
// speedup vs baseline: 1.0332x; 1.0332x over previous
#include <cuda_runtime.h>
#include <cuda_bf16.h>
#include <math.h>

#define GRID_N 4096

// ---- Bit-exact replica of XLA:CPU GenerateVF32Exp (validated R0-R16) ----
__device__ __forceinline__ float exp_xla_cpu(float input) {
    const float exp_hi = 88.3762626647950f;
    const float exp_lo = -88.3762626647949f;
    const float LOG2EF = 1.44269504088896341f;
    const float C1 = 0.693359375f;
    const float C2 = -2.12194440e-4f;
    const float p0 = 1.9875691500E-4f;
    const float p1 = 1.3981999507E-3f;
    const float p2 = 8.3334519073E-3f;
    const float p3 = 4.1665795894E-2f;
    const float p4 = 1.6666665459E-1f;
    const float p5 = 5.0000001201E-1f;

    float xc = fminf(fmaxf(input, exp_lo), exp_hi);
    float fx = floorf(__fmaf_rn(xc, LOG2EF, 0.5f));
    float tmp = __fmul_rn(C1, fx);
    float z   = __fmul_rn(C2, fx);
    float x   = __fsub_rn(xc, tmp);
    x = __fsub_rn(x, z);
    float z2 = __fmul_rn(x, x);

    float y = __fmaf_rn(x, p0, p1);
    y = __fmaf_rn(y, x, p2);
    y = __fmaf_rn(y, x, p3);
    y = __fmaf_rn(y, x, p4);
    y = __fmaf_rn(y, x, p5);
    y = __fmaf_rn(y, z2, x);
    y = __fadd_rn(y, 1.0f);

    int emm0 = (int)fx;
    emm0 = (emm0 + 0x7f) << 23;
    float two_m = __int_as_float(emm0);

    return fmaxf(__fmul_rn(y, two_m), input);
}

__device__ __forceinline__ float sigm(float v) {
    float e = exp_xla_cpu(-v);
    return __fdiv_rn(1.0f, __fadd_rn(1.0f, e));
}

__device__ __forceinline__ float relu_f(float v) { return fmaxf(v, 0.0f); }

// Windowed _gen_index, direct __ldg (validated bit-exact R8-R16).
__device__ float gen_index_window(const float* __restrict__ g,
                                  float g0, float gl, float a) {
    const float rstep = 1.0f / 2047.5f;  // fl(1/2047.5) (XLA const-div rewrite)
    float ac = fminf(fmaxf(a, gl), g0);

    float frac = __fdiv_rn(__fsub_rn(g0, ac), __fsub_rn(g0, gl));
    int c = __float2int_rn(__fmul_rn(frac, 4095.0f));

    int idxs[9];
    float vals[9];
#pragma unroll
    for (int k = 0; k < 9; k++) {
        int i = c - 4 + k;
        i = i < 0 ? 0 : (i > GRID_N - 1 ? GRID_N - 1 : i);
        idxs[k] = i;
        vals[k] = __ldg(&g[i]);
    }

    float best = __int_as_float(0x7f800000);
    int arg = idxs[0];
    float garg = vals[0];
    int argk = 0;
#pragma unroll
    for (int k = 0; k < 9; k++) {
        float d = fabsf(__fsub_rn(ac, vals[k]));
        if (d < best) { best = d; arg = idxs[k]; garg = vals[k]; argk = k; }
    }

    int shift = (garg > ac) ? 1 : 0;
    arg += shift;

    float hi, lo;
    int km1 = argk + shift - 1;
    int k0  = argk + shift;
    bool fast = (km1 >= 0) && (k0 <= 8) &&
                (idxs[km1] == arg - 1) && (idxs[k0] == arg) &&
                (arg >= 1) && (arg <= GRID_N - 1);
    if (fast) {
        hi = vals[km1];
        lo = vals[k0];
    } else {
        hi = (arg == 0) ? gl : __ldg(&g[arg - 1]);
        int lo_idx = arg > GRID_N - 1 ? GRID_N - 1 : arg;
        lo = __ldg(&g[lo_idx]);
    }

    float A = __fmul_rn(__fdiv_rn(__fsub_rn(hi, ac), __fsub_rn(hi, lo)), rstep);
    float B = __fmul_rn((float)(arg - 1), rstep);
    return __fsub_rn(__fadd_rn(A, B), 1.0f);
}

// Reference _bilinear on a [4096,4096] row-major table.
__device__ float bilinear(const float* __restrict__ t, float gx, float gy) {
    const float Wm1 = 4095.0f;
    float pxr = __fmul_rn(__fmul_rn(__fadd_rn(gx, 1.0f), 0.5f), Wm1);
    float pyr = __fmul_rn(__fmul_rn(__fadd_rn(gy, 1.0f), 0.5f), Wm1);
    float px = fminf(fmaxf(pxr, 0.0f), Wm1);
    float py = fminf(fmaxf(pyr, 0.0f), Wm1);
    float x0f = floorf(px);
    float y0f = floorf(py);
    float wx = __fsub_rn(px, x0f);
    float wy = __fsub_rn(py, y0f);
    float omwx = __fsub_rn(1.0f, wx);
    float omwy = __fsub_rn(1.0f, wy);
    int x0 = (int)x0f; x0 = max(0, min(x0, GRID_N - 1));
    int x1 = min(x0 + 1, GRID_N - 1);
    int y0 = (int)y0f; y0 = max(0, min(y0, GRID_N - 1));
    int y1 = min(y0 + 1, GRID_N - 1);
    float t00 = __ldg(&t[(long)y0 * GRID_N + x0]);
    float t01 = __ldg(&t[(long)y0 * GRID_N + x1]);
    float t10 = __ldg(&t[(long)y1 * GRID_N + x0]);
    float t11 = __ldg(&t[(long)y1 * GRID_N + x1]);
    float m00 = __fmul_rn(__fmul_rn(t00, omwx), omwy);
    float m01 = __fmul_rn(__fmul_rn(t01, wx), omwy);
    float m10 = __fmul_rn(__fmul_rn(t10, omwx), wy);
    float m11 = __fmul_rn(__fmul_rn(t11, wx), wy);
    return __fadd_rn(__fadd_rn(__fadd_rn(m00, m01), m10), m11);
}

// com slots: [0..4] gi1  [5..10] sigm(tw)  [11..14] sigm(tw2)
// [15..17] alpha1  [18..20] alpha2  [21..23] flags  [24..29] ybuf

__global__ void __launch_bounds__(32, 1)
rnn_kernel(const float* __restrict__ x,
           const float* __restrict__ s_weight,
           const float* __restrict__ t_weight,
           const float* __restrict__ t_weight2,
           const float* __restrict__ g,
           const float* __restrict__ res1,
           const float* __restrict__ res2,
           const float* __restrict__ alpha1,
           const float* __restrict__ alpha2,
           const float* __restrict__ soa_res1,
           const float* __restrict__ soa_res2,
           float* __restrict__ out, int out_size) {
    const unsigned FULL = 0xffffffffu;
    __shared__ float com[32];
    int lane = threadIdx.x;

    // Grid endpoints (independent loads, issue immediately on all lanes).
    float g0 = __ldg(&g[0]);
    float gl = __ldg(&g[GRID_N - 1]);

    // ---- Phase 0: scalar loads + sigmoids + stage-1 gen_index ----
    if (lane < 5) {
        float a = (lane < 3) ? __ldg(&x[lane * 2 + 1])
                             : sigm(__ldg(&s_weight[lane - 3]));
        com[lane] = gen_index_window(g, g0, gl, a);
    } else if (lane < 11) {
        com[lane] = sigm(__ldg(&t_weight[lane - 5]));
    } else if (lane < 15) {
        com[lane] = sigm(__ldg(&t_weight2[lane - 11]));
    } else if (lane < 18) {
        com[lane] = __ldg(&alpha1[lane - 15]);
    } else if (lane < 21) {
        com[lane] = __ldg(&alpha2[lane - 18]);
    } else if (lane < 24) {
        com[lane] = __ldg(&x[(lane - 21) * 2]);
    }
    __syncwarp();

    // ---- Phase 1: stage-1 bilinear (lanes 0-5) ----
    if (lane < 6) {
        int i = lane % 3;
        const float* tab = (lane < 3) ? res1 : res2;
        float gx = (lane < 3) ? com[3] : com[4];
        com[24 + lane] = bilinear(tab, gx, com[i]);
    }
    __syncwarp();

    // ---- Phase 2+3: lanes 0-4 recompute yvec locally (bit-identical),
    // lanes 0-3 stage-2 gen_index (result in r2), lane 4 regu (in reguv) ----
    float r2 = 0.0f;
    float reguv = 0.0f;
    if (lane < 5) {
        float w1[3], w2[3];
#pragma unroll
        for (int i = 0; i < 3; i++) {
            float flag = com[21 + i];
            float s1 = (flag == 1.0f) ? com[24 + i] : 0.0f;
            float s2 = (flag == 2.0f) ? com[27 + i] : 0.0f;
            w1[i] = __fmul_rn(s1, com[15 + i]);
            w2[i] = __fmul_rn(s2, com[18 + i]);
        }
        float y1v[2], y2v[2];
#pragma unroll
        for (int j = 0; j < 2; j++) {
            float tw0 = com[5 + 0 * 2 + j];
            float tw1 = com[5 + 1 * 2 + j];
            float tw2 = com[5 + 2 * 2 + j];
            y1v[j] = __fmaf_rn(w1[2], tw2,
                      __fmaf_rn(w1[1], tw1, __fmul_rn(w1[0], tw0)));
            y2v[j] = __fmaf_rn(w2[2], tw2,
                      __fmaf_rn(w2[1], tw1, __fmul_rn(w2[0], tw0)));
        }

        if (lane < 4) {
            // lane0: y1v[0], lane1: y2v[0], lane2: y1v[1], lane3: y2v[1]
            float a = (lane & 1) ? y2v[lane >> 1] : y1v[lane >> 1];
            r2 = gen_index_window(g, g0, gl, a);
        } else {
            float a10 = y1v[0], a11 = y1v[1];
            float a20 = y2v[0], a21 = y2v[1];
            float tA, tB, r1a, r1b, r2a, r2b;
            tA = relu_f(__fsub_rn(__fsub_rn(a10, g0), 0.001f));
            tB = relu_f(__fsub_rn(__fadd_rn(gl, 0.001f), a10));
            r1a = __fdiv_rn(__fadd_rn(tA, tB), __fmul_rn(a10, 2.0f));
            tA = relu_f(__fsub_rn(__fsub_rn(a20, g0), 0.001f));
            tB = relu_f(__fsub_rn(__fadd_rn(gl, 0.001f), a20));
            r1b = __fdiv_rn(__fadd_rn(tA, tB), __fmul_rn(a20, 2.0f));
            tA = relu_f(__fsub_rn(__fsub_rn(a11, g0), 0.001f));
            tB = relu_f(__fsub_rn(__fadd_rn(gl, 0.001f), a11));
            r2a = __fdiv_rn(__fadd_rn(tA, tB), __fmul_rn(a11, 2.0f));
            tA = relu_f(__fsub_rn(__fsub_rn(a21, g0), 0.001f));
            tB = relu_f(__fsub_rn(__fadd_rn(gl, 0.001f), a21));
            r2b = __fdiv_rn(__fadd_rn(tA, tB), __fmul_rn(a21, 2.0f));
            float regu1 = __fadd_rn(r1a, r1b);
            float regu2 = __fadd_rn(r2a, r2b);
            reguv = __fadd_rn(regu1, regu2);
        }
    }

    // ---- Phase 4: gi2 via shfl (no barrier), stage-2 bilinear (lanes 0-1) ----
    // lane l needs gy = gi2[2l] (from lane 2l), gx = gi2[2l+1] (from lane 2l+1).
    float s2gy = __shfl_sync(FULL, r2, (lane << 1) & 31);
    float s2gx = __shfl_sync(FULL, r2, ((lane << 1) + 1) & 31);

    float ys = 0.0f;
    if (lane < 2) {
        const float* tab = (lane == 0) ? soa_res1 : soa_res2;
        ys = bilinear(tab, s2gx, s2gy);
    }
    float y_2 = __shfl_sync(FULL, ys, 1);
    float regu_t = __shfl_sync(FULL, reguv, 4);

    if (lane == 0) {
        float y_1 = ys;
        float tw00 = com[11], tw01 = com[12];
        float tw10 = com[13], tw11 = com[14];

        float o0 = __fmaf_rn(y_2, tw10, __fmul_rn(y_1, tw00));
        float o1 = __fmaf_rn(y_2, tw11, __fmul_rn(y_1, tw01));
        float o2 = regu_t;

        if (out_size > 0) out[0] = o0;
        if (out_size > 1) out[1] = o1;
        if (out_size > 2) out[2] = o2;
    }
}

extern "C" void kernel_launch(void* const* d_in, const int* in_sizes, int n_in,
                              void* d_out, int out_size) {
    const float* x         = (const float*)d_in[0];
    const float* s_weight  = (const float*)d_in[1];
    const float* t_weight  = (const float*)d_in[2];
    const float* t_weight2 = (const float*)d_in[3];
    const float* g         = (const float*)d_in[4];
    const float* res1      = (const float*)d_in[5];
    const float* res2      = (const float*)d_in[6];
    const float* alpha1    = (const float*)d_in[7];
    const float* alpha2    = (const float*)d_in[8];
    const float* soa_res1  = (const float*)d_in[9];
    const float* soa_res2  = (const float*)d_in[10];
    float* out = (float*)d_out;

    rnn_kernel<<<1, 32>>>(x, s_weight, t_weight, t_weight2, g, res1, res2,
                          alpha1, alpha2, soa_res1, soa_res2, out, out_size);
}